// round 1
// baseline (speedup 1.0000x reference)
#include <cuda_runtime.h>
#include <math.h>

#define GRID_S   14
#define NCELL    (GRID_S * GRID_S)   // 196
#define NCLS     20
#define MAXOBJ   20
#define THREADS  256

// Global accumulators (device globals; no allocation allowed)
struct Accum {
    double sum_noobj;
    double sum_objconf;
    double sum_xy;
    double sum_wh;
    double sum_clc;
    unsigned long long n_noobj;
    unsigned long long n_resp;
    unsigned long long n_obj;
};
__device__ Accum g_acc;

__global__ void yolo_init_kernel() {
    g_acc.sum_noobj = 0.0;
    g_acc.sum_objconf = 0.0;
    g_acc.sum_xy = 0.0;
    g_acc.sum_wh = 0.0;
    g_acc.sum_clc = 0.0;
    g_acc.n_noobj = 0ull;
    g_acc.n_resp = 0ull;
    g_acc.n_obj = 0ull;
}

__inline__ __device__ float warpReduceF(float v) {
    #pragma unroll
    for (int o = 16; o > 0; o >>= 1) v += __shfl_down_sync(0xffffffffu, v, o);
    return v;
}
__inline__ __device__ int warpReduceI(int v) {
    #pragma unroll
    for (int o = 16; o > 0; o >>= 1) v += __shfl_down_sync(0xffffffffu, v, o);
    return v;
}

__global__ void __launch_bounds__(THREADS, 1)
yolo_main_kernel(const float* __restrict__ pred,
                 const float* __restrict__ target) {
    // Shared: per-image conf target [2][cell][5] + class bitmask per cell
    __shared__ float    s_conf[2][NCELL][5];        // 1960 floats
    __shared__ unsigned s_clsmask[NCELL];           // 196 ints
    // Object staging (parallel precompute, sequential commit)
    __shared__ float s_obj_f[MAXOBJ][4];            // offx, offy, w, h
    __shared__ int   s_obj_i[MAXOBJ][4];            // valid, mi, cell, cls
    // Reduction staging
    __shared__ float s_redf[8][5];
    __shared__ int   s_redi[8][3];

    const int b   = blockIdx.x;
    const int tid = threadIdx.x;

    // ---- Phase A: zero shared target state ----
    for (int i = tid; i < 2 * NCELL * 5; i += THREADS)
        ((float*)s_conf)[i] = 0.0f;
    for (int i = tid; i < NCELL; i += THREADS)
        s_clsmask[i] = 0u;

    // ---- Phase B1: per-object precompute (parallel; depends only on pred/target) ----
    if (tid < MAXOBJ) {
        const float* t = target + ((long long)b * MAXOBJ + tid) * 5;
        float x1 = t[0], y1 = t[1], x2 = t[2], y2 = t[3], cls = t[4];
        float s5 = x1 + y1 + x2 + y2 + cls;
        int valid = (s5 != 0.0f) ? 1 : 0;

        const float fg = (float)GRID_S;
        float cx = (x1 + x2) * 0.5f * fg;
        float cy = (y1 + y2) * 0.5f * fg;
        float w  = x2 - x1;
        float h  = y2 - y1;
        int gx = (int)floorf(cx); gx = min(max(gx, 0), GRID_S - 1);
        int gy = (int)floorf(cy); gy = min(max(gy, 0), GRID_S - 1);
        float offx = cx - (float)gx;
        float offy = cy - (float)gy;

        // IoU of the two predicted boxes at (gy,gx) vs this target
        const float* pb = pred + (((long long)b * NCELL) + gy * GRID_S + gx) * 30;
        float tcx = offx / fg, tcy = offy / fg;
        float t_ltx = tcx - 0.5f * w, t_lty = tcy - 0.5f * h;
        float t_rbx = tcx + 0.5f * w, t_rby = tcy + 0.5f * h;
        float a2 = (t_rbx - t_ltx) * (t_rby - t_lty);

        float iou[2];
        #pragma unroll
        for (int j = 0; j < 2; j++) {
            float px = pb[j * 5 + 1] / fg;
            float py = pb[j * 5 + 2] / fg;
            float pw = pb[j * 5 + 3];
            float ph = pb[j * 5 + 4];
            float p_ltx = px - 0.5f * pw, p_lty = py - 0.5f * ph;
            float p_rbx = px + 0.5f * pw, p_rby = py + 0.5f * ph;
            float ltx = fmaxf(p_ltx, t_ltx), lty = fmaxf(p_lty, t_lty);
            float rbx = fminf(p_rbx, t_rbx), rby = fminf(p_rby, t_rby);
            float wi = fmaxf(rbx - ltx, 0.0f);
            float hi = fmaxf(rby - lty, 0.0f);
            float inter = wi * hi;
            float a1 = (p_rbx - p_ltx) * (p_rby - p_lty);
            iou[j] = inter / (a1 + a2 - inter);
        }
        int mi = (iou[1] > iou[0]) ? 1 : 0;   // argmax: first index on ties

        s_obj_i[tid][0] = valid;
        s_obj_i[tid][1] = mi;
        s_obj_i[tid][2] = gy * GRID_S + gx;
        s_obj_i[tid][3] = (int)cls;
        s_obj_f[tid][0] = offx;
        s_obj_f[tid][1] = offy;
        s_obj_f[tid][2] = w;
        s_obj_f[tid][3] = h;
    }
    __syncthreads();

    // ---- Phase B2: sequential commit (preserves last-write-wins ordering) ----
    if (tid == 0) {
        #pragma unroll
        for (int o = 0; o < MAXOBJ; o++) {
            if (s_obj_i[o][0]) {
                int mi = s_obj_i[o][1];
                int cell = s_obj_i[o][2];
                s_conf[mi][cell][0] = 1.0f;
                s_conf[mi][cell][1] = s_obj_f[o][0];
                s_conf[mi][cell][2] = s_obj_f[o][1];
                s_conf[mi][cell][3] = s_obj_f[o][2];
                s_conf[mi][cell][4] = s_obj_f[o][3];
                s_clsmask[cell] |= (1u << s_obj_i[o][3]);
            }
        }
    }
    __syncthreads();

    // ---- Phase C: per-cell loss accumulation ----
    float l_noobj = 0.0f, l_objconf = 0.0f, l_xy = 0.0f, l_wh = 0.0f, l_clc = 0.0f;
    int c_noobj = 0, c_resp = 0, c_obj = 0;

    for (int cell = tid; cell < NCELL; cell += THREADS) {
        const float* p = pred + (((long long)b * NCELL) + cell) * 30;
        float c0 = s_conf[0][cell][0];
        float c1 = s_conf[1][cell][0];
        float csum = c0 + c1;                 // exact: values in {0,1}
        bool obj   = (csum == 1.0f);
        bool noobj = (csum == 0.0f);

        #pragma unroll
        for (int j = 0; j < 2; j++) {
            float pc = p[j * 5 + 0];
            if (noobj) { l_noobj += pc * pc; c_noobj++; }
            bool bset = ((j == 0 ? c0 : c1) == 1.0f);
            if (obj && bset) {
                c_resp++;
                float d = pc - 1.0f;
                l_objconf += d * d;
                float dx = p[j * 5 + 1] - s_conf[j][cell][1];
                float dy = p[j * 5 + 2] - s_conf[j][cell][2];
                l_xy += dx * dx + dy * dy;
                float dw = sqrtf(p[j * 5 + 3]) - sqrtf(s_conf[j][cell][3]);
                float dh = sqrtf(p[j * 5 + 4]) - sqrtf(s_conf[j][cell][4]);
                l_wh += dw * dw + dh * dh;
            }
        }
        if (obj) {
            c_obj++;
            unsigned mask = s_clsmask[cell];
            #pragma unroll
            for (int c = 0; c < NCLS; c++) {
                float t = ((mask >> c) & 1u) ? 1.0f : 0.0f;
                float d = p[10 + c] - t;
                l_clc += d * d;
            }
        }
    }

    // ---- Block reduction ----
    int wid = tid >> 5, lane = tid & 31;
    l_noobj   = warpReduceF(l_noobj);
    l_objconf = warpReduceF(l_objconf);
    l_xy      = warpReduceF(l_xy);
    l_wh      = warpReduceF(l_wh);
    l_clc     = warpReduceF(l_clc);
    c_noobj   = warpReduceI(c_noobj);
    c_resp    = warpReduceI(c_resp);
    c_obj     = warpReduceI(c_obj);
    if (lane == 0) {
        s_redf[wid][0] = l_noobj;
        s_redf[wid][1] = l_objconf;
        s_redf[wid][2] = l_xy;
        s_redf[wid][3] = l_wh;
        s_redf[wid][4] = l_clc;
        s_redi[wid][0] = c_noobj;
        s_redi[wid][1] = c_resp;
        s_redi[wid][2] = c_obj;
    }
    __syncthreads();
    if (tid == 0) {
        float tn = 0, to = 0, txy = 0, twh = 0, tc = 0;
        int   in = 0, ir = 0, io = 0;
        #pragma unroll
        for (int wv = 0; wv < THREADS / 32; wv++) {
            tn  += s_redf[wv][0];
            to  += s_redf[wv][1];
            txy += s_redf[wv][2];
            twh += s_redf[wv][3];
            tc  += s_redf[wv][4];
            in  += s_redi[wv][0];
            ir  += s_redi[wv][1];
            io  += s_redi[wv][2];
        }
        atomicAdd(&g_acc.sum_noobj,   (double)tn);
        atomicAdd(&g_acc.sum_objconf, (double)to);
        atomicAdd(&g_acc.sum_xy,      (double)txy);
        atomicAdd(&g_acc.sum_wh,      (double)twh);
        atomicAdd(&g_acc.sum_clc,     (double)tc);
        atomicAdd(&g_acc.n_noobj, (unsigned long long)in);
        atomicAdd(&g_acc.n_resp,  (unsigned long long)ir);
        atomicAdd(&g_acc.n_obj,   (unsigned long long)io);
    }
}

__global__ void yolo_final_kernel(float* __restrict__ out) {
    double n_resp  = (double)g_acc.n_resp;
    double n_noobj = (double)g_acc.n_noobj;
    double n_obj   = (double)g_acc.n_obj;
    double loss_xy      = g_acc.sum_xy      / (n_resp * 2.0);
    double loss_wh      = g_acc.sum_wh      / (n_resp * 2.0);
    double objconf_loss = g_acc.sum_objconf / n_resp;
    double noobj_loss   = g_acc.sum_noobj   / n_noobj;
    double loss_clc     = g_acc.sum_clc     / (n_obj * (double)NCLS);
    out[0] = (float)(5.0 * (loss_xy + loss_wh) + objconf_loss +
                     0.5 * noobj_loss + loss_clc);
}

extern "C" void kernel_launch(void* const* d_in, const int* in_sizes, int n_in,
                              void* d_out, int out_size) {
    const float* pred   = (const float*)d_in[0];
    const float* target = (const float*)d_in[1];
    int bs = in_sizes[1] / (MAXOBJ * 5);

    yolo_init_kernel<<<1, 1>>>();
    yolo_main_kernel<<<bs, THREADS>>>(pred, target);
    yolo_final_kernel<<<1, 1>>>((float*)d_out);
}